// round 1
// baseline (speedup 1.0000x reference)
#include <cuda_runtime.h>
#include <cuda_bf16.h>
#include <math.h>

// Problem dims (fixed by the reference)
#define NROWS 16384   // B*C = 1024*16
#define HDIM  1024    // D = H = EH = TH
#define NEXP  6
#define NTASK 3
#define TOPK  3

// ---------------------------------------------------------------------------
// Scratch (device globals: allocation-free)
// ---------------------------------------------------------------------------
__device__ __align__(256) float g_h1[(long)NROWS * HDIM];            // 64 MB
__device__ __align__(256) float g_h [(long)NROWS * HDIM];            // 64 MB
__device__ __align__(256) float g_eh[(long)NEXP * NROWS * HDIM];     // 402 MB
__device__ __align__(256) float g_eo[(long)NEXP * NROWS * HDIM];     // 402 MB
__device__ __align__(256) float g_mo[(long)NTASK * NROWS * HDIM];    // 201 MB
__device__ __align__(256) float g_gates[(long)NTASK * NROWS * NEXP];

// ---------------------------------------------------------------------------
// SGEMM: C[bz] = op(A[bz] @ B[bz] + bias[bz]);  A[M,K], B[K,N], row-major.
// Tiles: 128x128x8, 256 threads, 8x8 per-thread microtile.
// Requires M%128==0, N%128==0, K%8==0 (true for all calls here).
// ---------------------------------------------------------------------------
#define BM 128
#define BN 128
#define BK 8
#define TM 8
#define TN 8

template <bool RELU>
__global__ __launch_bounds__(256)
void sgemm_kernel(const float* __restrict__ A, const float* __restrict__ Bm,
                  const float* __restrict__ bias, float* __restrict__ C,
                  int M, int K, int N,
                  long sA, long sB, long sBias, long sC)
{
    const int bz = blockIdx.z;
    A    += (long)bz * sA;
    Bm   += (long)bz * sB;
    bias += (long)bz * sBias;
    C    += (long)bz * sC;

    __shared__ float As[BK][BM];
    __shared__ float Bs[BK][BN];

    const int tid = threadIdx.x;      // 0..255
    const int tx  = tid & 15;         // col group
    const int ty  = tid >> 4;         // row group

    const int row0 = blockIdx.y * BM;
    const int col0 = blockIdx.x * BN;

    // A tile loader: one float4 per thread. row = tid/2, k = (tid%2)*4
    const int a_row = tid >> 1;
    const int a_k   = (tid & 1) * 4;
    // B tile loader: one float4 per thread. k = tid/32, col = (tid%32)*4
    const int b_k   = tid >> 5;
    const int b_col = (tid & 31) * 4;

    float acc[TM][TN];
#pragma unroll
    for (int i = 0; i < TM; i++)
#pragma unroll
        for (int j = 0; j < TN; j++) acc[i][j] = 0.f;

    float a_frag[TM], b_frag[TN];

    for (int k0 = 0; k0 < K; k0 += BK) {
        float4 av = *reinterpret_cast<const float4*>(
            &A[(long)(row0 + a_row) * K + k0 + a_k]);
        As[a_k + 0][a_row] = av.x;
        As[a_k + 1][a_row] = av.y;
        As[a_k + 2][a_row] = av.z;
        As[a_k + 3][a_row] = av.w;

        float4 bv = *reinterpret_cast<const float4*>(
            &Bm[(long)(k0 + b_k) * N + col0 + b_col]);
        *reinterpret_cast<float4*>(&Bs[b_k][b_col]) = bv;

        __syncthreads();
#pragma unroll
        for (int kk = 0; kk < BK; kk++) {
#pragma unroll
            for (int i = 0; i < TM; i += 4)
                *reinterpret_cast<float4*>(&a_frag[i]) =
                    *reinterpret_cast<const float4*>(&As[kk][ty * TM + i]);
#pragma unroll
            for (int j = 0; j < TN; j += 4)
                *reinterpret_cast<float4*>(&b_frag[j]) =
                    *reinterpret_cast<const float4*>(&Bs[kk][tx * TN + j]);
#pragma unroll
            for (int i = 0; i < TM; i++)
#pragma unroll
                for (int j = 0; j < TN; j++)
                    acc[i][j] = fmaf(a_frag[i], b_frag[j], acc[i][j]);
        }
        __syncthreads();
    }

    // Epilogue: bias (+ relu), vectorized store
#pragma unroll
    for (int i = 0; i < TM; i++) {
        const long r = row0 + ty * TM + i;
#pragma unroll
        for (int j = 0; j < TN; j += 4) {
            const int c = col0 + tx * TN + j;
            float4 v = make_float4(acc[i][j], acc[i][j+1], acc[i][j+2], acc[i][j+3]);
            v.x += bias[c + 0]; v.y += bias[c + 1];
            v.z += bias[c + 2]; v.w += bias[c + 3];
            if (RELU) {
                v.x = fmaxf(v.x, 0.f); v.y = fmaxf(v.y, 0.f);
                v.z = fmaxf(v.z, 0.f); v.w = fmaxf(v.w, 0.f);
            }
            *reinterpret_cast<float4*>(&C[r * N + c]) = v;
        }
    }
}

// ---------------------------------------------------------------------------
// Tower GEMM with fused final reduction:
//   th = relu(mo[t] @ tw1[t] + tb1[t]);  out[t,n] += th[n,:] . tw2[t,:]
// Same mainloop as sgemm; epilogue reduces over the 128-col tile and
// atomicAdds per (t,row). out must be pre-initialized to tb2[t].
// ---------------------------------------------------------------------------
__global__ __launch_bounds__(256)
void tower_kernel(const float* __restrict__ A, const float* __restrict__ Bm,
                  const float* __restrict__ bias, const float* __restrict__ w2,
                  float* __restrict__ out,
                  int M, int K, int N,
                  long sA, long sB, long sBias, long sW2)
{
    const int bz = blockIdx.z;           // task t
    A    += (long)bz * sA;
    Bm   += (long)bz * sB;
    bias += (long)bz * sBias;
    w2   += (long)bz * sW2;
    float* out_t = out + (long)bz * M;

    __shared__ float As[BK][BM];
    __shared__ float Bs[BK][BN];

    const int tid = threadIdx.x;
    const int tx  = tid & 15;
    const int ty  = tid >> 4;

    const int row0 = blockIdx.y * BM;
    const int col0 = blockIdx.x * BN;

    const int a_row = tid >> 1;
    const int a_k   = (tid & 1) * 4;
    const int b_k   = tid >> 5;
    const int b_col = (tid & 31) * 4;

    float acc[TM][TN];
#pragma unroll
    for (int i = 0; i < TM; i++)
#pragma unroll
        for (int j = 0; j < TN; j++) acc[i][j] = 0.f;

    float a_frag[TM], b_frag[TN];

    for (int k0 = 0; k0 < K; k0 += BK) {
        float4 av = *reinterpret_cast<const float4*>(
            &A[(long)(row0 + a_row) * K + k0 + a_k]);
        As[a_k + 0][a_row] = av.x;
        As[a_k + 1][a_row] = av.y;
        As[a_k + 2][a_row] = av.z;
        As[a_k + 3][a_row] = av.w;

        float4 bv = *reinterpret_cast<const float4*>(
            &Bm[(long)(k0 + b_k) * N + col0 + b_col]);
        *reinterpret_cast<float4*>(&Bs[b_k][b_col]) = bv;

        __syncthreads();
#pragma unroll
        for (int kk = 0; kk < BK; kk++) {
#pragma unroll
            for (int i = 0; i < TM; i += 4)
                *reinterpret_cast<float4*>(&a_frag[i]) =
                    *reinterpret_cast<const float4*>(&As[kk][ty * TM + i]);
#pragma unroll
            for (int j = 0; j < TN; j += 4)
                *reinterpret_cast<float4*>(&b_frag[j]) =
                    *reinterpret_cast<const float4*>(&Bs[kk][tx * TN + j]);
#pragma unroll
            for (int i = 0; i < TM; i++)
#pragma unroll
                for (int j = 0; j < TN; j++)
                    acc[i][j] = fmaf(a_frag[i], b_frag[j], acc[i][j]);
        }
        __syncthreads();
    }

    // Epilogue: relu(acc+bias) * w2, reduce over this block's 128 cols
    float partial[TM];
#pragma unroll
    for (int i = 0; i < TM; i++) partial[i] = 0.f;
#pragma unroll
    for (int i = 0; i < TM; i++) {
#pragma unroll
        for (int j = 0; j < TN; j++) {
            const int c = col0 + tx * TN + j;
            float v = fmaxf(acc[i][j] + bias[c], 0.f);
            partial[i] = fmaf(v, w2[c], partial[i]);
        }
    }
    // Threads with the same ty are 16 consecutive lanes in a warp:
    // reduce over tx with shfl_down (16-lane groups).
#pragma unroll
    for (int off = 8; off > 0; off >>= 1)
#pragma unroll
        for (int i = 0; i < TM; i++)
            partial[i] += __shfl_down_sync(0xffffffffu, partial[i], off);

    if (tx == 0) {
#pragma unroll
        for (int i = 0; i < TM; i++)
            atomicAdd(&out_t[row0 + ty * TM + i], partial[i]);
    }
}

// ---------------------------------------------------------------------------
// Gating: one warp per (t, n). logits[e] = h[n,:] . w_gate[t,:,e];
// top-3 -> softmax -> dense gates[t,n,0..5].
// ---------------------------------------------------------------------------
__global__ __launch_bounds__(256)
void gate_kernel(const float* __restrict__ h, const float* __restrict__ wg,
                 float* __restrict__ gates)
{
    const int warp = (blockIdx.x * blockDim.x + threadIdx.x) >> 5;
    const int lane = threadIdx.x & 31;
    if (warp >= NTASK * NROWS) return;
    const int t = warp / NROWS;
    const int n = warp - t * NROWS;

    float acc[NEXP];
#pragma unroll
    for (int e = 0; e < NEXP; e++) acc[e] = 0.f;

    const float* hrow = h + (long)n * HDIM;
    const float* wt   = wg + (long)t * HDIM * NEXP;
    for (int hh = lane; hh < HDIM; hh += 32) {
        const float hv = hrow[hh];
        const float* wr = wt + (long)hh * NEXP;
#pragma unroll
        for (int e = 0; e < NEXP; e++)
            acc[e] = fmaf(hv, wr[e], acc[e]);
    }
#pragma unroll
    for (int off = 16; off > 0; off >>= 1)
#pragma unroll
        for (int e = 0; e < NEXP; e++)
            acc[e] += __shfl_xor_sync(0xffffffffu, acc[e], off);

    if (lane == 0) {
        float v[NEXP];
#pragma unroll
        for (int e = 0; e < NEXP; e++) v[e] = acc[e];
        int   ti[TOPK];
        float tv[TOPK];
#pragma unroll
        for (int s = 0; s < TOPK; s++) {
            int bi = 0; float bv = v[0];
#pragma unroll
            for (int e = 1; e < NEXP; e++)
                if (v[e] > bv) { bv = v[e]; bi = e; }
            ti[s] = bi; tv[s] = bv; v[bi] = -INFINITY;
        }
        const float m = tv[0];   // sorted descending
        float w[TOPK], s = 0.f;
#pragma unroll
        for (int k = 0; k < TOPK; k++) { w[k] = expf(tv[k] - m); s += w[k]; }
        const float inv = 1.f / s;
        float gv[NEXP];
#pragma unroll
        for (int e = 0; e < NEXP; e++) gv[e] = 0.f;
#pragma unroll
        for (int k = 0; k < TOPK; k++) gv[ti[k]] = w[k] * inv;
        float* gp = gates + ((long)t * NROWS + n) * NEXP;
#pragma unroll
        for (int e = 0; e < NEXP; e++) gp[e] = gv[e];
    }
}

// ---------------------------------------------------------------------------
// Gate combine: mo[t,n,h] = sum_e gates[t,n,e] * eo[e,n,h]
// ---------------------------------------------------------------------------
__global__ __launch_bounds__(256)
void combine_kernel(const float* __restrict__ eo, const float* __restrict__ gates,
                    float* __restrict__ mo)
{
    const long nh  = (long)NROWS * HDIM;
    const long idx = (long)blockIdx.x * blockDim.x + threadIdx.x;
    if (idx >= nh) return;
    const int n = (int)(idx >> 10);   // HDIM = 1024

    float v[NEXP];
#pragma unroll
    for (int e = 0; e < NEXP; e++) v[e] = eo[(long)e * nh + idx];

#pragma unroll
    for (int t = 0; t < NTASK; t++) {
        const float* gp = gates + ((long)t * NROWS + n) * NEXP;
        float r = 0.f;
#pragma unroll
        for (int e = 0; e < NEXP; e++) r = fmaf(gp[e], v[e], r);
        mo[(long)t * nh + idx] = r;
    }
}

// ---------------------------------------------------------------------------
// out init: out[t, n] = tb2[t]
// ---------------------------------------------------------------------------
__global__ void init_out_kernel(float* __restrict__ out, const float* __restrict__ tb2)
{
    const int i = blockIdx.x * blockDim.x + threadIdx.x;
    if (i < NTASK * NROWS) out[i] = tb2[i / NROWS];
}

// ---------------------------------------------------------------------------
extern "C" void kernel_launch(void* const* d_in, const int* in_sizes, int n_in,
                              void* d_out, int out_size)
{
    const float* cls   = (const float*)d_in[0];
    const float* fc1w  = (const float*)d_in[1];
    const float* fc1b  = (const float*)d_in[2];
    const float* fc2w  = (const float*)d_in[3];
    const float* fc2b  = (const float*)d_in[4];
    const float* wgate = (const float*)d_in[5];
    const float* ew1   = (const float*)d_in[6];
    const float* eb1   = (const float*)d_in[7];
    const float* ew2   = (const float*)d_in[8];
    const float* eb2   = (const float*)d_in[9];
    const float* tw1   = (const float*)d_in[10];
    const float* tb1   = (const float*)d_in[11];
    const float* tw2   = (const float*)d_in[12];
    const float* tb2   = (const float*)d_in[13];
    float* out = (float*)d_out;

    float *h1, *h, *eh, *eo, *mo, *gates;
    cudaGetSymbolAddress((void**)&h1,    g_h1);
    cudaGetSymbolAddress((void**)&h,     g_h);
    cudaGetSymbolAddress((void**)&eh,    g_eh);
    cudaGetSymbolAddress((void**)&eo,    g_eo);
    cudaGetSymbolAddress((void**)&mo,    g_mo);
    cudaGetSymbolAddress((void**)&gates, g_gates);

    const dim3 blk(256);
    const long HH = (long)HDIM * HDIM;        // 1024*1024
    const long NH = (long)NROWS * HDIM;       // 16384*1024

    // shared bottom
    sgemm_kernel<true ><<<dim3(8, 128, 1), blk>>>(cls, fc1w, fc1b, h1,
                                                  NROWS, HDIM, HDIM, 0, 0, 0, 0);
    sgemm_kernel<false><<<dim3(8, 128, 1), blk>>>(h1, fc2w, fc2b, h,
                                                  NROWS, HDIM, HDIM, 0, 0, 0, 0);
    // gating (T*N warps, 8 warps per block)
    gate_kernel<<<(NTASK * NROWS) / 8, blk>>>(h, wgate, gates);

    // experts
    sgemm_kernel<true ><<<dim3(8, 128, NEXP), blk>>>(h, ew1, eb1, eh,
                                                     NROWS, HDIM, HDIM,
                                                     0, HH, HDIM, NH);
    sgemm_kernel<false><<<dim3(8, 128, NEXP), blk>>>(eh, ew2, eb2, eo,
                                                     NROWS, HDIM, HDIM,
                                                     NH, HH, HDIM, NH);
    // gate combine
    combine_kernel<<<(unsigned)(NH / 256), blk>>>(eo, gates, mo);

    // towers (fused final dot via atomics)
    init_out_kernel<<<(NTASK * NROWS + 255) / 256, blk>>>(out, tb2);
    tower_kernel<<<dim3(8, 128, NTASK), blk>>>(mo, tw1, tb1, tw2, out,
                                               NROWS, HDIM, HDIM,
                                               NH, HH, HDIM, HDIM);
}